// round 5
// baseline (speedup 1.0000x reference)
#include <cuda_runtime.h>

#define IN_F   128
#define OUT_F  128
#define MAX_NODES 10000
#define MAX_EDGES 640000
#define TILE_N 32
#define KK     256     // fused K dimension: [agg_norm | x]
#define KC     32      // K-chunk size for combine

// Scratch (no allocations allowed anywhere)
__device__ float4 g_agg4[MAX_NODES * (IN_F / 4)];  // normalized aggregate
__device__ int    g_cnt[MAX_NODES];                // in-degree counts
__device__ int    g_off[MAX_NODES + 1];            // CSR offsets
__device__ int    g_cur[MAX_NODES];                // fill cursors
__device__ int    g_srcl[MAX_EDGES];               // CSR-ordered src indices
__device__ int    g_is64;                          // 1 if edge_index is int64

// Dtype-agnostic edge-index load (uniform branch on detected flag)
__device__ __forceinline__ int load_idx(const void* __restrict__ ei, long long pos) {
    if (g_is64) return (int)((const long long*)ei)[pos];
    return ((const int*)ei)[pos];
}

// ---------------------------------------------------------------------------
// 0) detect edge_index dtype: int64 values < 2^32 have zero high words.
// ---------------------------------------------------------------------------
__global__ void detect_kernel(const unsigned int* __restrict__ ei_w, int E) {
    // Inspect odd 32-bit words of the first min(128, E) "int64" slots.
    // If ANY is nonzero, the buffer must be int32.
    unsigned int acc = 0;
    int n = (E < 128) ? E : 128;
    for (int i = 0; i < n; i++) acc |= ei_w[2 * i + 1];
    g_is64 = (acc == 0) ? 1 : 0;
}

// ---------------------------------------------------------------------------
// 1) zero counts
// ---------------------------------------------------------------------------
__global__ void zero_kernel(int n_nodes) {
    int i = blockIdx.x * blockDim.x + threadIdx.x;
    if (i < n_nodes) g_cnt[i] = 0;
}

// ---------------------------------------------------------------------------
// 2) in-degree histogram (scalar int atomics, 10K counters)
// ---------------------------------------------------------------------------
__global__ void deg_kernel(const void* __restrict__ ei, int E, int n_nodes) {
    int e = blockIdx.x * blockDim.x + threadIdx.x;
    if (e < E) {
        int dst = load_idx(ei, (long long)E + e);
        dst = min(max(dst, 0), n_nodes - 1);
        atomicAdd(&g_cnt[dst], 1);
    }
}

// ---------------------------------------------------------------------------
// 3) exclusive scan of counts -> offsets (+ cursor copy). Single block.
// ---------------------------------------------------------------------------
__global__ __launch_bounds__(1024, 1)
void scan_kernel(int n_nodes) {
    __shared__ int part[1024];
    const int PER = 16;                 // 1024*16 = 16384 >= 10000
    int t = threadIdx.x;
    int base = t * PER;
    int s = 0;
    for (int i = 0; i < PER; i++) {
        int idx = base + i;
        if (idx < n_nodes) s += g_cnt[idx];
    }
    part[t] = s;
    __syncthreads();
    // Hillis-Steele inclusive scan over 1024 partials
    for (int off = 1; off < 1024; off <<= 1) {
        int v = (t >= off) ? part[t - off] : 0;
        __syncthreads();
        part[t] += v;
        __syncthreads();
    }
    int run = (t == 0) ? 0 : part[t - 1];  // exclusive base for this chunk
    for (int i = 0; i < PER; i++) {
        int idx = base + i;
        if (idx < n_nodes) {
            g_off[idx] = run;
            g_cur[idx] = run;
            run += g_cnt[idx];
        }
    }
    if (t == 1023) g_off[n_nodes] = part[1023];
}

// ---------------------------------------------------------------------------
// 4) bucket fill: place each edge's src into its dst's CSR segment
// ---------------------------------------------------------------------------
__global__ void fill_kernel(const void* __restrict__ ei, int E, int n_nodes) {
    int e = blockIdx.x * blockDim.x + threadIdx.x;
    if (e < E) {
        int src = load_idx(ei, e);
        int dst = load_idx(ei, (long long)E + e);
        src = min(max(src, 0), n_nodes - 1);
        dst = min(max(dst, 0), n_nodes - 1);
        int pos = atomicAdd(&g_cur[dst], 1);
        if (pos < MAX_EDGES) g_srcl[pos] = src;
    }
}

// ---------------------------------------------------------------------------
// 5) gather: one warp per node. 32 lanes x float4 cover the 128-f row.
//    Neighbor index is warp-uniform (L1 broadcast load). Atomic-free.
// ---------------------------------------------------------------------------
__global__ __launch_bounds__(256)
void gather_kernel(const float* __restrict__ x, int n_nodes) {
    int warp = (int)((blockIdx.x * (long long)blockDim.x + threadIdx.x) >> 5);
    int lane = threadIdx.x & 31;
    if (warp >= n_nodes) return;

    int beg = g_off[warp];
    int end = g_off[warp + 1];
    const float4* x4 = (const float4*)x;

    float4 acc = make_float4(0.f, 0.f, 0.f, 0.f);
    int j = beg;
    // unrolled by 4 for MLP
    for (; j + 4 <= end; j += 4) {
        int i0 = g_srcl[j + 0];
        int i1 = g_srcl[j + 1];
        int i2 = g_srcl[j + 2];
        int i3 = g_srcl[j + 3];
        float4 v0 = x4[(size_t)i0 * (IN_F / 4) + lane];
        float4 v1 = x4[(size_t)i1 * (IN_F / 4) + lane];
        float4 v2 = x4[(size_t)i2 * (IN_F / 4) + lane];
        float4 v3 = x4[(size_t)i3 * (IN_F / 4) + lane];
        acc.x += v0.x + v1.x + v2.x + v3.x;
        acc.y += v0.y + v1.y + v2.y + v3.y;
        acc.z += v0.z + v1.z + v2.z + v3.z;
        acc.w += v0.w + v1.w + v2.w + v3.w;
    }
    for (; j < end; j++) {
        int idx = g_srcl[j];
        float4 v = x4[(size_t)idx * (IN_F / 4) + lane];
        acc.x += v.x; acc.y += v.y; acc.z += v.z; acc.w += v.w;
    }
    int deg = end - beg;
    float inv = 1.0f / (float)((deg == 0) ? 1 : deg);
    acc.x *= inv; acc.y *= inv; acc.z *= inv; acc.w *= inv;
    g_agg4[(size_t)warp * (IN_F / 4) + lane] = acc;
}

// ---------------------------------------------------------------------------
// 6) combine: out = agg_norm @ W^T + x @ B^T as one fused 256-K GEMM.
//    K-chunked, STATIC shared memory only (~21 KB).
// ---------------------------------------------------------------------------
__global__ __launch_bounds__(256)
void combine_kernel(const float* __restrict__ x,
                    const float* __restrict__ W,
                    const float* __restrict__ B,
                    float* __restrict__ out, int n_nodes) {
    __shared__ float Wsh[KC][OUT_F + 4];   // [kk][o], row stride 132 (16B-aligned)
    __shared__ float Ash[TILE_N][KC + 1];  // [node][kk]

    int tid = threadIdx.x;
    int n0 = blockIdx.x * TILE_N;
    const float* agg = (const float*)g_agg4;

    int og = tid & 31;   // outputs [og*4, og*4+3]
    int ng = tid >> 5;   // nodes   [ng*4, ng*4+3]

    float4 acc[4];
#pragma unroll
    for (int j = 0; j < 4; j++) acc[j] = make_float4(0.f, 0.f, 0.f, 0.f);

    for (int kc = 0; kc < KK; kc += KC) {
        // Load W-or-B chunk transposed: Wsh[kk][o] = Wt[kc+kk][o]
        for (int i = tid; i < KC * OUT_F; i += 256) {
            int kk = i & (KC - 1);
            int o  = i >> 5;
            int kg = kc + kk;
            Wsh[kk][o] = (kg < IN_F) ? W[o * IN_F + kg]
                                     : B[o * IN_F + (kg - IN_F)];
        }
        // Load A chunk: 32 nodes x 32 k, from agg (k<128) or x (k>=128)
        for (int i = tid; i < TILE_N * KC; i += 256) {
            int nl = i >> 5;
            int kk = i & (KC - 1);
            int n  = n0 + nl;
            int kg = kc + kk;
            float v = 0.0f;
            if (n < n_nodes)
                v = (kg < IN_F) ? agg[n * IN_F + kg]
                                : x[n * IN_F + (kg - IN_F)];
            Ash[nl][kk] = v;
        }
        __syncthreads();

#pragma unroll
        for (int kk = 0; kk < KC; kk++) {
            float4 w = *(const float4*)&Wsh[kk][og * 4];
#pragma unroll
            for (int j = 0; j < 4; j++) {
                float a = Ash[ng * 4 + j][kk];
                acc[j].x += w.x * a;
                acc[j].y += w.y * a;
                acc[j].z += w.z * a;
                acc[j].w += w.w * a;
            }
        }
        __syncthreads();
    }

#pragma unroll
    for (int j = 0; j < 4; j++) {
        int n = n0 + ng * 4 + j;
        if (n < n_nodes)
            *(float4*)(out + (size_t)n * OUT_F + og * 4) = acc[j];
    }
}

// ---------------------------------------------------------------------------
// kernel_launch
// Inputs: x [10000,128] f32, edge_index [2,640000] (int32 OR int64 — detected
// at runtime), W [128,128] f32, B [128,128] f32. Output: [10000,128] f32.
// ---------------------------------------------------------------------------
extern "C" void kernel_launch(void* const* d_in, const int* in_sizes, int n_in,
                              void* d_out, int out_size) {
    const float* x  = (const float*)d_in[0];
    const void*  ei = d_in[1];
    const float* W  = (const float*)d_in[2];
    const float* B  = (const float*)d_in[3];
    float*       out = (float*)d_out;

    int n_nodes = in_sizes[0] / IN_F;
    int E       = in_sizes[1] / 2;

    detect_kernel<<<1, 1>>>((const unsigned int*)ei, E);
    zero_kernel<<<(n_nodes + 255) / 256, 256>>>(n_nodes);
    deg_kernel<<<(E + 255) / 256, 256>>>(ei, E, n_nodes);
    scan_kernel<<<1, 1024>>>(n_nodes);
    fill_kernel<<<(E + 255) / 256, 256>>>(ei, E, n_nodes);
    {
        long long threads = (long long)n_nodes * 32;
        int blocks = (int)((threads + 255) / 256);
        gather_kernel<<<blocks, 256>>>(x, n_nodes);
    }
    combine_kernel<<<(n_nodes + TILE_N - 1) / TILE_N, 256>>>(x, W, B, out, n_nodes);
}

// round 6
// speedup vs baseline: 1.0948x; 1.0948x over previous
#include <cuda_runtime.h>

#define IN_F   128
#define OUT_F  128
#define MAX_NODES 10000
#define MAX_EDGES 640000
#define TILE_N 32
#define KK     256     // fused K dimension: [agg_norm | x]
#define KC     32      // K-chunk size for combine

// Scratch (no allocations allowed anywhere)
__device__ float4 g_agg4[MAX_NODES * (IN_F / 4)];  // normalized aggregate
__device__ int    g_cnt[MAX_NODES];                // in-degree counts
__device__ int    g_off[MAX_NODES + 1];            // CSR offsets
__device__ int    g_cur[MAX_NODES];                // fill cursors
__device__ int    g_srcl[MAX_EDGES];               // CSR-ordered src indices
__device__ int    g_is64;                          // 1 if edge_index is int64

// Dtype-agnostic edge-index load (uniform branch on detected flag)
__device__ __forceinline__ int load_idx(const void* __restrict__ ei, long long pos) {
    if (g_is64) return (int)((const long long*)ei)[pos];
    return ((const int*)ei)[pos];
}

// ---------------------------------------------------------------------------
// 1) zero counts + dtype detect (warp 0 of block 0, parallel ballot)
// ---------------------------------------------------------------------------
__global__ void zero_detect_kernel(const unsigned int* __restrict__ ei_w,
                                   int E, int n_nodes) {
    int i = blockIdx.x * blockDim.x + threadIdx.x;
    if (i < n_nodes) g_cnt[i] = 0;
    if (blockIdx.x == 0 && threadIdx.x < 32) {
        // If edge_index is int64 with values < 2^32, every odd 32-bit word is 0.
        unsigned int v = (threadIdx.x < E) ? ei_w[2 * threadIdx.x + 1] : 0u;
        unsigned int any = __ballot_sync(0xffffffffu, v != 0u);
        if (threadIdx.x == 0) g_is64 = (any == 0u) ? 1 : 0;
    }
}

// ---------------------------------------------------------------------------
// 2) in-degree histogram (scalar int atomics, 10K counters)
// ---------------------------------------------------------------------------
__global__ void deg_kernel(const void* __restrict__ ei, int E, int n_nodes) {
    int e = blockIdx.x * blockDim.x + threadIdx.x;
    if (e < E) {
        int dst = load_idx(ei, (long long)E + e);
        dst = min(max(dst, 0), n_nodes - 1);
        atomicAdd(&g_cnt[dst], 1);
    }
}

// ---------------------------------------------------------------------------
// 3) exclusive scan of counts -> offsets. Single block, warp-shuffle
//    hierarchical scan: 2 barriers total (vs ~20 in Hillis-Steele version).
// ---------------------------------------------------------------------------
__global__ __launch_bounds__(1024, 1)
void scan_kernel(int n_nodes) {
    const int PER = 10;                 // 1024*10 = 10240 >= 10000
    __shared__ int wsum[32];
    int t = threadIdx.x, lane = t & 31, wid = t >> 5;
    int base = t * PER;

    int loc[PER];
    int s = 0;
#pragma unroll
    for (int i = 0; i < PER; i++) {
        int idx = base + i;
        int c = (idx < n_nodes) ? g_cnt[idx] : 0;
        loc[i] = s;                     // exclusive within thread
        s += c;
    }
    // warp inclusive scan of per-thread sums
    int v = s;
#pragma unroll
    for (int o = 1; o < 32; o <<= 1) {
        int u = __shfl_up_sync(0xffffffffu, v, o);
        if (lane >= o) v += u;
    }
    if (lane == 31) wsum[wid] = v;
    __syncthreads();
    if (wid == 0) {
        int w = wsum[lane];
#pragma unroll
        for (int o = 1; o < 32; o <<= 1) {
            int u = __shfl_up_sync(0xffffffffu, w, o);
            if (lane >= o) w += u;
        }
        wsum[lane] = w;
    }
    __syncthreads();
    int wbase = (wid == 0) ? 0 : wsum[wid - 1];
    int tbase = wbase + (v - s);        // exclusive base for this thread
#pragma unroll
    for (int i = 0; i < PER; i++) {
        int idx = base + i;
        if (idx < n_nodes) {
            int off = tbase + loc[i];
            g_off[idx] = off;
            g_cur[idx] = off;
        }
    }
    if (t == 0) g_off[n_nodes] = wsum[31];
}

// ---------------------------------------------------------------------------
// 4) bucket fill: place each edge's src into its dst's CSR segment
// ---------------------------------------------------------------------------
__global__ void fill_kernel(const void* __restrict__ ei, int E, int n_nodes) {
    int e = blockIdx.x * blockDim.x + threadIdx.x;
    if (e < E) {
        int src = load_idx(ei, e);
        int dst = load_idx(ei, (long long)E + e);
        src = min(max(src, 0), n_nodes - 1);
        dst = min(max(dst, 0), n_nodes - 1);
        int pos = atomicAdd(&g_cur[dst], 1);
        if (pos < MAX_EDGES) g_srcl[pos] = src;
    }
}

// ---------------------------------------------------------------------------
// 5) gather: one warp per node. 32 lanes x float4 cover the 128-f row.
//    Unroll-8 neighbor loads for MLP. Atomic-free.
// ---------------------------------------------------------------------------
__global__ __launch_bounds__(256)
void gather_kernel(const float* __restrict__ x, int n_nodes) {
    int warp = (int)((blockIdx.x * (long long)blockDim.x + threadIdx.x) >> 5);
    int lane = threadIdx.x & 31;
    if (warp >= n_nodes) return;

    int beg = g_off[warp];
    int end = g_off[warp + 1];
    const float4* x4 = (const float4*)x;

    float4 acc = make_float4(0.f, 0.f, 0.f, 0.f);
    int j = beg;
    for (; j + 8 <= end; j += 8) {
        int i0 = g_srcl[j + 0], i1 = g_srcl[j + 1];
        int i2 = g_srcl[j + 2], i3 = g_srcl[j + 3];
        int i4 = g_srcl[j + 4], i5 = g_srcl[j + 5];
        int i6 = g_srcl[j + 6], i7 = g_srcl[j + 7];
        float4 v0 = x4[(size_t)i0 * (IN_F / 4) + lane];
        float4 v1 = x4[(size_t)i1 * (IN_F / 4) + lane];
        float4 v2 = x4[(size_t)i2 * (IN_F / 4) + lane];
        float4 v3 = x4[(size_t)i3 * (IN_F / 4) + lane];
        float4 v4 = x4[(size_t)i4 * (IN_F / 4) + lane];
        float4 v5 = x4[(size_t)i5 * (IN_F / 4) + lane];
        float4 v6 = x4[(size_t)i6 * (IN_F / 4) + lane];
        float4 v7 = x4[(size_t)i7 * (IN_F / 4) + lane];
        acc.x += (v0.x + v1.x) + (v2.x + v3.x) + (v4.x + v5.x) + (v6.x + v7.x);
        acc.y += (v0.y + v1.y) + (v2.y + v3.y) + (v4.y + v5.y) + (v6.y + v7.y);
        acc.z += (v0.z + v1.z) + (v2.z + v3.z) + (v4.z + v5.z) + (v6.z + v7.z);
        acc.w += (v0.w + v1.w) + (v2.w + v3.w) + (v4.w + v5.w) + (v6.w + v7.w);
    }
    for (; j < end; j++) {
        int idx = g_srcl[j];
        float4 v = x4[(size_t)idx * (IN_F / 4) + lane];
        acc.x += v.x; acc.y += v.y; acc.z += v.z; acc.w += v.w;
    }
    int deg = end - beg;
    float inv = 1.0f / (float)((deg == 0) ? 1 : deg);
    acc.x *= inv; acc.y *= inv; acc.z *= inv; acc.w *= inv;
    g_agg4[(size_t)warp * (IN_F / 4) + lane] = acc;
}

// ---------------------------------------------------------------------------
// 6) combine: out = agg_norm @ W^T + x @ B^T as one fused 256-K GEMM.
//    Packed f32x2 FMA (Blackwell dual-fp32): accumulators hold node-pairs,
//    A tile stored transposed so a node pair is one ld.shared.b64.
// ---------------------------------------------------------------------------
__global__ __launch_bounds__(256)
void combine_kernel(const float* __restrict__ x,
                    const float* __restrict__ W,
                    const float* __restrict__ B,
                    float* __restrict__ out, int n_nodes) {
    __shared__ float Wsh[KC][OUT_F + 4];      // [kk][o], row stride 132
    __shared__ float Ash[KC][TILE_N + 2];     // transposed [kk][node], stride 34 (8B-aligned rows)

    int tid = threadIdx.x;
    int n0 = blockIdx.x * TILE_N;
    const float* agg = (const float*)g_agg4;

    int og = tid & 31;   // outputs [og*4, og*4+3]
    int ng = tid >> 5;   // nodes   [ng*4, ng*4+3] -> pairs (4ng,4ng+1), (4ng+2,4ng+3)

    unsigned long long acc[2][4];
#pragma unroll
    for (int p = 0; p < 2; p++)
#pragma unroll
        for (int o = 0; o < 4; o++) acc[p][o] = 0ull;

    for (int kc = 0; kc < KK; kc += KC) {
        // W-or-B chunk transposed: Wsh[kk][o] = Wt[kc+kk][o]
        for (int i = tid; i < KC * OUT_F; i += 256) {
            int kk = i & (KC - 1);
            int o  = i >> 5;
            int kg = kc + kk;
            Wsh[kk][o] = (kg < IN_F) ? W[o * IN_F + kg]
                                     : B[o * IN_F + (kg - IN_F)];
        }
        // A chunk transposed: Ash[kk][node]
        for (int i = tid; i < TILE_N * KC; i += 256) {
            int nl = i >> 5;
            int kk = i & (KC - 1);
            int n  = n0 + nl;
            int kg = kc + kk;
            float v = 0.0f;
            if (n < n_nodes)
                v = (kg < IN_F) ? agg[n * IN_F + kg]
                                : x[n * IN_F + (kg - IN_F)];
            Ash[kk][nl] = v;
        }
        __syncthreads();

#pragma unroll
        for (int kk = 0; kk < KC; kk++) {
            float4 w = *(const float4*)&Wsh[kk][og * 4];
            unsigned long long wx, wy, wz, ww;
            asm("mov.b64 %0, {%1, %1};" : "=l"(wx) : "f"(w.x));
            asm("mov.b64 %0, {%1, %1};" : "=l"(wy) : "f"(w.y));
            asm("mov.b64 %0, {%1, %1};" : "=l"(wz) : "f"(w.z));
            asm("mov.b64 %0, {%1, %1};" : "=l"(ww) : "f"(w.w));
#pragma unroll
            for (int p = 0; p < 2; p++) {
                unsigned long long a2 =
                    *(const unsigned long long*)&Ash[kk][ng * 4 + p * 2];
                asm("fma.rn.f32x2 %0, %1, %2, %0;" : "+l"(acc[p][0]) : "l"(wx), "l"(a2));
                asm("fma.rn.f32x2 %0, %1, %2, %0;" : "+l"(acc[p][1]) : "l"(wy), "l"(a2));
                asm("fma.rn.f32x2 %0, %1, %2, %0;" : "+l"(acc[p][2]) : "l"(wz), "l"(a2));
                asm("fma.rn.f32x2 %0, %1, %2, %0;" : "+l"(acc[p][3]) : "l"(ww), "l"(a2));
            }
        }
        __syncthreads();
    }

    // Epilogue: unpack node-pair accumulators, store one float4 per node
#pragma unroll
    for (int p = 0; p < 2; p++) {
        float4 r0, r1;   // r0 = even node of pair, r1 = odd node
        asm("mov.b64 {%0, %1}, %2;" : "=f"(r0.x), "=f"(r1.x) : "l"(acc[p][0]));
        asm("mov.b64 {%0, %1}, %2;" : "=f"(r0.y), "=f"(r1.y) : "l"(acc[p][1]));
        asm("mov.b64 {%0, %1}, %2;" : "=f"(r0.z), "=f"(r1.z) : "l"(acc[p][2]));
        asm("mov.b64 {%0, %1}, %2;" : "=f"(r0.w), "=f"(r1.w) : "l"(acc[p][3]));
        int na = n0 + ng * 4 + p * 2;
        int nb = na + 1;
        if (na < n_nodes) *(float4*)(out + (size_t)na * OUT_F + og * 4) = r0;
        if (nb < n_nodes) *(float4*)(out + (size_t)nb * OUT_F + og * 4) = r1;
    }
}

// ---------------------------------------------------------------------------
// kernel_launch
// Inputs: x [10000,128] f32, edge_index [2,640000] (int32 OR int64 — detected
// at runtime), W [128,128] f32, B [128,128] f32. Output: [10000,128] f32.
// ---------------------------------------------------------------------------
extern "C" void kernel_launch(void* const* d_in, const int* in_sizes, int n_in,
                              void* d_out, int out_size) {
    const float* x  = (const float*)d_in[0];
    const void*  ei = d_in[1];
    const float* W  = (const float*)d_in[2];
    const float* B  = (const float*)d_in[3];
    float*       out = (float*)d_out;

    int n_nodes = in_sizes[0] / IN_F;
    int E       = in_sizes[1] / 2;

    zero_detect_kernel<<<(n_nodes + 255) / 256, 256>>>((const unsigned int*)ei, E, n_nodes);
    deg_kernel<<<(E + 255) / 256, 256>>>(ei, E, n_nodes);
    scan_kernel<<<1, 1024>>>(n_nodes);
    fill_kernel<<<(E + 255) / 256, 256>>>(ei, E, n_nodes);
    {
        long long threads = (long long)n_nodes * 32;
        int blocks = (int)((threads + 255) / 256);
        gather_kernel<<<blocks, 256>>>(x, n_nodes);
    }
    combine_kernel<<<(n_nodes + TILE_N - 1) / TILE_N, 256>>>(x, W, B, out, n_nodes);
}